// round 6
// baseline (speedup 1.0000x reference)
#include <cuda_runtime.h>
#include <cuda_bf16.h>
#include <cstdint>

// ---------------------------------------------------------------------------
// Problem constants
// ---------------------------------------------------------------------------
#define BB 16
#define NQS 2048
#define NKS 2048
#define DHD 128
#define OUT_ELEMS (BB * NQS * DHD)                 // 4194304
#define ATTN_ELEMS ((long long)BB * NQS * NKS)     // 67108864

#define TWO_PI_F  6.283185307179586f
#define INV2W2_F  0.8105694691387022f   // 1/(2*(pi/4)^2)
#define SCALE_F   0.08838834764831843f  // 1/sqrt(128)

// ---------------------------------------------------------------------------
// SMEM layout (byte offsets). Row-major bf16 tiles padded +16B/row so that
// all fragment LDS are bank-conflict-free (bank = 4*(lane/4) + lane%4).
// ---------------------------------------------------------------------------
#define SM_GATE  0        // 2048 f32 (gate * scale)            8192 B
#define SM_RS    8192     // 128 f32 rowsum                      512 B
#define SM_QHI   8704     // 128 x 136 bf16                    34816 B
#define SM_QLO   43520
#define SM_KHI   78336    // 64 x 136 bf16                     17408 B
#define SM_KLO   95744
#define SM_VTHI  113152   // 128 x 72 bf16 (row = dh, col=key) 18432 B
#define SM_VTLO  131584
#define SM_PHI   150016   // 128 x 72 bf16 (row = q, col=key)  18432 B
#define SM_PLO   168448
#define SMEM_TOTAL 186880

#define QSTR 272   // bytes per row (136 bf16)
#define KSTR 272
#define VSTR 144   // 72 bf16
#define PSTR 144

__device__ float g_inv_l[BB * NQS];

// ---------------------------------------------------------------------------
// mma.sync m16n8k16 bf16 (row.col), D = A*B + D   — valid on plain sm_103
// ---------------------------------------------------------------------------
#define MMA16816(d, a, b0_, b1_) \
  asm volatile("mma.sync.aligned.m16n8k16.row.col.f32.bf16.bf16.f32 " \
    "{%0,%1,%2,%3}, {%4,%5,%6,%7}, {%8,%9}, {%0,%1,%2,%3};" \
    : "+f"((d)[0]), "+f"((d)[1]), "+f"((d)[2]), "+f"((d)[3]) \
    : "r"((a)[0]), "r"((a)[1]), "r"((a)[2]), "r"((a)[3]), "r"(b0_), "r"(b1_))

__device__ __forceinline__ uint32_t pk2(__nv_bfloat16 a, __nv_bfloat16 b) {
  __nv_bfloat162 t; t.x = a; t.y = b;
  return *reinterpret_cast<uint32_t*>(&t);
}
__device__ __forceinline__ void splitf(float x, __nv_bfloat16& h, __nv_bfloat16& l) {
  h = __float2bfloat16_rn(x);
  l = __float2bfloat16_rn(x - __bfloat162float(h));
}

// ---------------------------------------------------------------------------
// Main kernel: one CTA per (batch, 128-q-row tile). 256 threads = 8 warps.
// ---------------------------------------------------------------------------
__global__ void __launch_bounds__(256)
gpa_main_kernel(const float* __restrict__ Q, const float* __restrict__ K,
                const float* __restrict__ V, const float* __restrict__ phases,
                float* __restrict__ out, float* __restrict__ attn,
                int write_attn) {
  extern __shared__ char smem[];
  const int tid = threadIdx.x;
  const int wid = tid >> 5;
  const int lane = tid & 31;
  const int g = lane >> 2;       // 0..7  fragment row group
  const int c = lane & 3;        // 0..3  fragment col group
  const int wm = wid >> 1;       // 0..3  M-warp (32 q rows each)
  const int wn = wid & 1;        // 0..1  N-warp

  const int b = blockIdx.y;
  const int q0 = blockIdx.x * 128;
  const float* Qb = Q + ((size_t)b * NQS + q0) * DHD;
  const float* Kb = K + (size_t)b * NKS * DHD;
  const float* Vb = V + (size_t)b * NKS * DHD;

  float* gate_s = (float*)(smem + SM_GATE);
  float* rsbuf  = (float*)(smem + SM_RS);

  // --- gate precompute (includes 1/sqrt(dh)) ---
  for (int k = tid; k < NKS; k += 256) {
    float ph = phases[k];
    float pd = fminf(ph, TWO_PI_F - ph);
    gate_s[k] = __expf(-pd * pd * INV2W2_F) * SCALE_F;
  }

  // --- Q tile -> SMEM bf16 hi/lo (128 x 128) ---
  {
    const float4* qp = (const float4*)Qb;
    for (int it = tid; it < 4096; it += 256) {
      int row = it >> 5;
      int c4 = (it & 31) << 2;
      float4 v = qp[it];
      __nv_bfloat16 hx,lx,hy,ly,hz,lz,hw,lw;
      splitf(v.x,hx,lx); splitf(v.y,hy,ly); splitf(v.z,hz,lz); splitf(v.w,hw,lw);
      int off = row * QSTR + c4 * 2;
      *(uint32_t*)(smem + SM_QHI + off)     = pk2(hx,hy);
      *(uint32_t*)(smem + SM_QHI + off + 4) = pk2(hz,hw);
      *(uint32_t*)(smem + SM_QLO + off)     = pk2(lx,ly);
      *(uint32_t*)(smem + SM_QLO + off + 4) = pk2(lz,lw);
    }
  }

  float o[2][8][4];      // persistent O accumulators: 32 rows x 64 dh per warp
#pragma unroll
  for (int i = 0; i < 2; i++)
#pragma unroll
    for (int j = 0; j < 8; j++)
#pragma unroll
      for (int e = 0; e < 4; e++) o[i][j][e] = 0.0f;

  float rs[2][2] = {{0.f,0.f},{0.f,0.f}};   // per-thread rowsum partials

  for (int kt = 0; kt < 32; kt++) {
    const int k0 = kt * 64;
    __syncthreads();   // prev iteration done reading K/V/P

    // --- K half-tile (64 keys x 128 dh) -> hi/lo SMEM ---
    {
      const float4* kp = (const float4*)(Kb + (size_t)k0 * DHD);
      for (int it = tid; it < 2048; it += 256) {
        int row = it >> 5;
        int c4 = (it & 31) << 2;
        float4 v = kp[it];
        __nv_bfloat16 hx,lx,hy,ly,hz,lz,hw,lw;
        splitf(v.x,hx,lx); splitf(v.y,hy,ly); splitf(v.z,hz,lz); splitf(v.w,hw,lw);
        int off = row * KSTR + c4 * 2;
        *(uint32_t*)(smem + SM_KHI + off)     = pk2(hx,hy);
        *(uint32_t*)(smem + SM_KHI + off + 4) = pk2(hz,hw);
        *(uint32_t*)(smem + SM_KLO + off)     = pk2(lx,ly);
        *(uint32_t*)(smem + SM_KLO + off + 4) = pk2(lz,lw);
      }
      // --- V half-tile transposed (row = dh, col = key) ---
      const float4* vp = (const float4*)(Vb + (size_t)k0 * DHD);
      for (int it = tid; it < 2048; it += 256) {
        int row = it >> 5;          // local key
        int c4 = (it & 31) << 2;    // dh base
        float4 v = vp[it];
        float ve[4] = {v.x, v.y, v.z, v.w};
#pragma unroll
        for (int e = 0; e < 4; e++) {
          __nv_bfloat16 h, l;
          splitf(ve[e], h, l);
          int off = (c4 + e) * VSTR + row * 2;
          *(__nv_bfloat16*)(smem + SM_VTHI + off) = h;
          *(__nv_bfloat16*)(smem + SM_VTLO + off) = l;
        }
      }
    }
    __syncthreads();

    // --- S = Q K^T  (warp tile 32 x 32, 3-term hi/lo) ---
    float s[2][4][4];
#pragma unroll
    for (int i = 0; i < 2; i++)
#pragma unroll
      for (int j = 0; j < 4; j++)
#pragma unroll
        for (int e = 0; e < 4; e++) s[i][j][e] = 0.0f;

#pragma unroll
    for (int kc = 0; kc < 8; kc++) {
      uint32_t ah[2][4], al[2][4];
#pragma unroll
      for (int i = 0; i < 2; i++) {
        const char* qh = smem + SM_QHI + (wm*32 + i*16 + g) * QSTR + (kc*16 + 2*c) * 2;
        ah[i][0] = *(const uint32_t*)(qh);
        ah[i][1] = *(const uint32_t*)(qh + 8*QSTR);
        ah[i][2] = *(const uint32_t*)(qh + 16);
        ah[i][3] = *(const uint32_t*)(qh + 8*QSTR + 16);
        const char* ql = smem + SM_QLO + (wm*32 + i*16 + g) * QSTR + (kc*16 + 2*c) * 2;
        al[i][0] = *(const uint32_t*)(ql);
        al[i][1] = *(const uint32_t*)(ql + 8*QSTR);
        al[i][2] = *(const uint32_t*)(ql + 16);
        al[i][3] = *(const uint32_t*)(ql + 8*QSTR + 16);
      }
#pragma unroll
      for (int j = 0; j < 4; j++) {
        const char* kh = smem + SM_KHI + (wn*32 + j*8 + g) * KSTR + (kc*16 + 2*c) * 2;
        uint32_t bh0 = *(const uint32_t*)(kh);
        uint32_t bh1 = *(const uint32_t*)(kh + 16);
        const char* kl = smem + SM_KLO + (wn*32 + j*8 + g) * KSTR + (kc*16 + 2*c) * 2;
        uint32_t bl0 = *(const uint32_t*)(kl);
        uint32_t bl1 = *(const uint32_t*)(kl + 16);
#pragma unroll
        for (int i = 0; i < 2; i++) {
          MMA16816(s[i][j], ah[i], bh0, bh1);
          MMA16816(s[i][j], ah[i], bl0, bl1);
          MMA16816(s[i][j], al[i], bh0, bh1);
        }
      }
    }

    // --- Epilogue: p = exp(s * gate); rowsum; P hi/lo -> SMEM; attn STG ---
#pragma unroll
    for (int i = 0; i < 2; i++) {
      const int lr = wm*32 + i*16 + g;   // local q row (and +8)
#pragma unroll
      for (int j = 0; j < 4; j++) {
        const int lc = wn*32 + j*8 + 2*c;   // local key col
        float2 gt = *(const float2*)(smem + SM_GATE + (size_t)(k0 + lc) * 4);
        float p00 = __expf(s[i][j][0] * gt.x);
        float p01 = __expf(s[i][j][1] * gt.y);
        float p10 = __expf(s[i][j][2] * gt.x);
        float p11 = __expf(s[i][j][3] * gt.y);
        rs[i][0] += p00 + p01;
        rs[i][1] += p10 + p11;
        __nv_bfloat16 h00,l00,h01,l01,h10,l10,h11,l11;
        splitf(p00,h00,l00); splitf(p01,h01,l01);
        splitf(p10,h10,l10); splitf(p11,h11,l11);
        int po = lr * PSTR + lc * 2;
        *(uint32_t*)(smem + SM_PHI + po)          = pk2(h00,h01);
        *(uint32_t*)(smem + SM_PHI + po + 8*PSTR) = pk2(h10,h11);
        *(uint32_t*)(smem + SM_PLO + po)          = pk2(l00,l01);
        *(uint32_t*)(smem + SM_PLO + po + 8*PSTR) = pk2(l10,l11);
        if (write_attn) {
          float* a0 = attn + ((size_t)(b * NQS + q0 + lr)) * NKS + (k0 + lc);
          *(float2*)a0 = make_float2(p00, p01);
          *(float2*)(a0 + (size_t)8 * NKS) = make_float2(p10, p11);
        }
      }
    }
    __syncthreads();   // P visible to all warps

    // --- O += P V  (warp tile 32 rows x 64 dh, keys 0..63, 3-term hi/lo) ---
#pragma unroll
    for (int kc = 0; kc < 4; kc++) {
      uint32_t ph_[2][4], pl_[2][4];
#pragma unroll
      for (int i = 0; i < 2; i++) {
        const char* pph = smem + SM_PHI + (wm*32 + i*16 + g) * PSTR + (kc*16 + 2*c) * 2;
        ph_[i][0] = *(const uint32_t*)(pph);
        ph_[i][1] = *(const uint32_t*)(pph + 8*PSTR);
        ph_[i][2] = *(const uint32_t*)(pph + 16);
        ph_[i][3] = *(const uint32_t*)(pph + 8*PSTR + 16);
        const char* ppl = smem + SM_PLO + (wm*32 + i*16 + g) * PSTR + (kc*16 + 2*c) * 2;
        pl_[i][0] = *(const uint32_t*)(ppl);
        pl_[i][1] = *(const uint32_t*)(ppl + 8*PSTR);
        pl_[i][2] = *(const uint32_t*)(ppl + 16);
        pl_[i][3] = *(const uint32_t*)(ppl + 8*PSTR + 16);
      }
#pragma unroll
      for (int j = 0; j < 8; j++) {
        const char* vh = smem + SM_VTHI + (wn*64 + j*8 + g) * VSTR + (kc*16 + 2*c) * 2;
        uint32_t bh0 = *(const uint32_t*)(vh);
        uint32_t bh1 = *(const uint32_t*)(vh + 16);
        const char* vl = smem + SM_VTLO + (wn*64 + j*8 + g) * VSTR + (kc*16 + 2*c) * 2;
        uint32_t bl0 = *(const uint32_t*)(vl);
        uint32_t bl1 = *(const uint32_t*)(vl + 16);
#pragma unroll
        for (int i = 0; i < 2; i++) {
          MMA16816(o[i][j], ph_[i], bh0, bh1);
          MMA16816(o[i][j], ph_[i], bl0, bl1);
          MMA16816(o[i][j], pl_[i], bh0, bh1);
        }
      }
    }
  }

  // --- Rowsum reduction: quad shfl, then combine the two N-warps ---
#pragma unroll
  for (int i = 0; i < 2; i++)
#pragma unroll
    for (int h = 0; h < 2; h++) {
      float v = rs[i][h];
      v += __shfl_xor_sync(0xffffffffu, v, 1);
      v += __shfl_xor_sync(0xffffffffu, v, 2);
      rs[i][h] = v;
    }
  if (wn == 0 && c == 0) {
#pragma unroll
    for (int i = 0; i < 2; i++)
#pragma unroll
      for (int h = 0; h < 2; h++)
        rsbuf[wm*32 + i*16 + h*8 + g] = rs[i][h];
  }
  __syncthreads();
  if (wn == 1 && c == 0) {
#pragma unroll
    for (int i = 0; i < 2; i++)
#pragma unroll
      for (int h = 0; h < 2; h++)
        rsbuf[wm*32 + i*16 + h*8 + g] += rs[i][h];
  }
  __syncthreads();

  if (tid < 128) g_inv_l[(size_t)b * NQS + q0 + tid] = 1.0f / rsbuf[tid];

  // --- Normalized output store ---
#pragma unroll
  for (int i = 0; i < 2; i++) {
    const int lr = wm*32 + i*16 + g;
    const float inv0 = 1.0f / rsbuf[lr];
    const float inv1 = 1.0f / rsbuf[lr + 8];
    float* o0 = out + ((size_t)(b * NQS + q0 + lr)) * DHD + wn*64 + 2*c;
#pragma unroll
    for (int j = 0; j < 8; j++) {
      *(float2*)(o0 + j*8) = make_float2(o[i][j][0] * inv0, o[i][j][1] * inv0);
      *(float2*)(o0 + (size_t)8 * DHD + j*8) =
          make_float2(o[i][j][2] * inv1, o[i][j][3] * inv1);
    }
  }
}

// ---------------------------------------------------------------------------
// Normalize pass: attention[b,q,k] *= 1/rowsum[b,q]
// ---------------------------------------------------------------------------
__global__ void gpa_norm_kernel(float* __restrict__ attn) {
  const size_t n4 = (size_t)ATTN_ELEMS / 4;
  const size_t stride = (size_t)gridDim.x * blockDim.x;
  float4* a = (float4*)attn;
  for (size_t j = (size_t)blockIdx.x * blockDim.x + threadIdx.x; j < n4; j += stride) {
    float inv = g_inv_l[j >> 9];   // 512 float4 per 2048-wide row
    float4 v = a[j];
    v.x *= inv; v.y *= inv; v.z *= inv; v.w *= inv;
    a[j] = v;
  }
}

// ---------------------------------------------------------------------------
// Launch
// ---------------------------------------------------------------------------
extern "C" void kernel_launch(void* const* d_in, const int* in_sizes, int n_in,
                              void* d_out, int out_size) {
  const float* Q  = (const float*)d_in[0];
  const float* K  = (const float*)d_in[1];
  const float* V  = (const float*)d_in[2];
  const float* ph = (const float*)d_in[3];
  float* out = (float*)d_out;

  const bool write_attn = ((long long)out_size >= (long long)OUT_ELEMS + ATTN_ELEMS);
  float* attn = out + OUT_ELEMS;

  static bool attr_set = false;
  if (!attr_set) {
    cudaFuncSetAttribute(gpa_main_kernel,
                         cudaFuncAttributeMaxDynamicSharedMemorySize, SMEM_TOTAL);
    attr_set = true;
  }

  dim3 grid(NQS / 128, BB);
  gpa_main_kernel<<<grid, 256, SMEM_TOTAL>>>(Q, K, V, ph, out, attn,
                                             write_attn ? 1 : 0);
  if (write_attn) {
    gpa_norm_kernel<<<4096, 256>>>(attn);
  }
}

// round 8
// speedup vs baseline: 1.5773x; 1.5773x over previous
#include <cuda_runtime.h>
#include <cuda_bf16.h>
#include <cstdint>

// ---------------------------------------------------------------------------
// Problem constants
// ---------------------------------------------------------------------------
#define BB 16
#define NQS 2048
#define NKS 2048
#define DHD 128
#define OUT_ELEMS (BB * NQS * DHD)                 // 4194304
#define ATTN_ELEMS ((long long)BB * NQS * NKS)     // 67108864

#define TWO_PI_F  6.283185307179586f
#define INV2W2_F  0.8105694691387022f   // 1/(2*(pi/4)^2)
#define SCALE_F   0.08838834764831843f  // 1/sqrt(128)

#define NTHR 512

// ---------------------------------------------------------------------------
// SMEM layout (byte offsets). Tiles padded so all fragment LDS/STS are
// bank-conflict-free (verified: lane bank = f(g,c) bijective per access).
// ---------------------------------------------------------------------------
#define SM_GATE  0         // 2048 f32                              8192 B
#define SM_RS    8192      // 128 f32 (inv rowsum)                   512 B
#define SM_RSP   8704      // 4 x 128 f32 partials                  2048 B
#define SM_QHI   10752     // 128 x 136 bf16 (QSTR=272)            34816 B
#define SM_QLO   45568
#define SM_KHI   80384     // 64 x 136 bf16 (KSTR=272)             17408 B
#define SM_KLO   97792
#define SM_VTHI  115200    // 128 x 66 bf16 (VSTR=132, odd words)  16896 B
#define SM_VTLO  132096
#define SM_PHI   148992    // 128 x 72 bf16 (PSTR=144)             18432 B
#define SM_PLO   167424
#define SMEM_TOTAL 185856

#define QSTR 272
#define KSTR 272
#define VSTR 132
#define PSTR 144

__device__ float g_inv_l[BB * NQS];

// ---------------------------------------------------------------------------
// mma.sync m16n8k16 bf16 (row.col), D = A*B + D  — valid on plain sm_103
// ---------------------------------------------------------------------------
#define MMA16816(d, a, b0_, b1_) \
  asm volatile("mma.sync.aligned.m16n8k16.row.col.f32.bf16.bf16.f32 " \
    "{%0,%1,%2,%3}, {%4,%5,%6,%7}, {%8,%9}, {%0,%1,%2,%3};" \
    : "+f"((d)[0]), "+f"((d)[1]), "+f"((d)[2]), "+f"((d)[3]) \
    : "r"((a)[0]), "r"((a)[1]), "r"((a)[2]), "r"((a)[3]), "r"(b0_), "r"(b1_))

__device__ __forceinline__ uint32_t pk2(__nv_bfloat16 a, __nv_bfloat16 b) {
  __nv_bfloat162 t; t.x = a; t.y = b;
  return *reinterpret_cast<uint32_t*>(&t);
}
__device__ __forceinline__ void splitf(float x, __nv_bfloat16& h, __nv_bfloat16& l) {
  h = __float2bfloat16_rn(x);
  l = __float2bfloat16_rn(x - __bfloat162float(h));
}
__device__ __forceinline__ uint32_t lds32(const char* p) {
  return *reinterpret_cast<const uint32_t*>(p);
}

// ---------------------------------------------------------------------------
// Main kernel: one CTA per (batch, 128-q tile). 512 threads = 16 warps
// (4 per SMSP for MMA latency hiding).
// ---------------------------------------------------------------------------
__global__ void __launch_bounds__(NTHR, 1)
gpa_main_kernel(const float* __restrict__ Q, const float* __restrict__ K,
                const float* __restrict__ V, const float* __restrict__ phases,
                float* __restrict__ out, float* __restrict__ attn,
                int write_attn) {
  extern __shared__ char smem[];
  const int tid = threadIdx.x;
  const int wid = tid >> 5;
  const int lane = tid & 31;
  const int g = lane >> 2;       // fragment row group 0..7
  const int c = lane & 3;        // fragment col group 0..3
  const int wm = wid >> 2;       // 0..3 : 32-q-row band
  const int wn = wid & 3;        // 0..3 : QK key stripe / PV dh stripe

  const int b = blockIdx.y;
  const int q0 = blockIdx.x * 128;
  const float* Qb = Q + ((size_t)b * NQS + q0) * DHD;
  const float* Kb = K + (size_t)b * NKS * DHD;
  const float* Vb = V + (size_t)b * NKS * DHD;

  float* gate_s = (float*)(smem + SM_GATE);
  float* rsbuf  = (float*)(smem + SM_RS);
  float* rsp    = (float*)(smem + SM_RSP);

  // --- gate precompute (includes 1/sqrt(dh)) ---
  for (int k = tid; k < NKS; k += NTHR) {
    float ph = phases[k];
    float pd = fminf(ph, TWO_PI_F - ph);
    gate_s[k] = __expf(-pd * pd * INV2W2_F) * SCALE_F;
  }

  // --- Q tile -> SMEM bf16 hi/lo (128 x 128) ---
  {
    const float4* qp = (const float4*)Qb;
    for (int it = tid; it < 4096; it += NTHR) {
      int row = it >> 5;
      int c4 = (it & 31) << 2;
      float4 v = qp[it];
      __nv_bfloat16 hx,lx,hy,ly,hz,lz,hw,lw;
      splitf(v.x,hx,lx); splitf(v.y,hy,ly); splitf(v.z,hz,lz); splitf(v.w,hw,lw);
      int off = row * QSTR + c4 * 2;
      *(uint32_t*)(smem + SM_QHI + off)     = pk2(hx,hy);
      *(uint32_t*)(smem + SM_QHI + off + 4) = pk2(hz,hw);
      *(uint32_t*)(smem + SM_QLO + off)     = pk2(lx,ly);
      *(uint32_t*)(smem + SM_QLO + off + 4) = pk2(lz,lw);
    }
  }

  float o[2][4][4];   // persistent O accumulators: 32 q x 32 dh per warp
#pragma unroll
  for (int i = 0; i < 2; i++)
#pragma unroll
    for (int j = 0; j < 4; j++)
#pragma unroll
      for (int e = 0; e < 4; e++) o[i][j][e] = 0.0f;

  float rs[2][2] = {{0.f,0.f},{0.f,0.f}};

  for (int kt = 0; kt < 32; kt++) {
    const int k0 = kt * 64;
    __syncthreads();   // previous iteration done reading K/V/P

    // --- K half-tile (64 keys x 128 dh) -> hi/lo SMEM ---
    {
      const float4* kp = (const float4*)(Kb + (size_t)k0 * DHD);
      for (int it = tid; it < 2048; it += NTHR) {
        int row = it >> 5;
        int c4 = (it & 31) << 2;
        float4 v = kp[it];
        __nv_bfloat16 hx,lx,hy,ly,hz,lz,hw,lw;
        splitf(v.x,hx,lx); splitf(v.y,hy,ly); splitf(v.z,hz,lz); splitf(v.w,hw,lw);
        int off = row * KSTR + c4 * 2;
        *(uint32_t*)(smem + SM_KHI + off)     = pk2(hx,hy);
        *(uint32_t*)(smem + SM_KHI + off + 4) = pk2(hz,hw);
        *(uint32_t*)(smem + SM_KLO + off)     = pk2(lx,ly);
        *(uint32_t*)(smem + SM_KLO + off + 4) = pk2(lz,lw);
      }
      // --- V half-tile transposed (row = dh, col = key), VSTR odd-word ---
      const float4* vp = (const float4*)(Vb + (size_t)k0 * DHD);
      for (int it = tid; it < 2048; it += NTHR) {
        int row = it >> 5;          // local key 0..63
        int c4 = (it & 31) << 2;    // dh base
        float4 v = vp[it];
        float ve[4] = {v.x, v.y, v.z, v.w};
#pragma unroll
        for (int e = 0; e < 4; e++) {
          __nv_bfloat16 h, l;
          splitf(ve[e], h, l);
          int off = (c4 + e) * VSTR + row * 2;
          *(__nv_bfloat16*)(smem + SM_VTHI + off) = h;
          *(__nv_bfloat16*)(smem + SM_VTLO + off) = l;
        }
      }
    }
    __syncthreads();

    // --- S = Q K^T  (warp tile 32q x 16k, 3-term hi/lo, term-major order) ---
    float s[2][2][4];
#pragma unroll
    for (int i = 0; i < 2; i++)
#pragma unroll
      for (int j = 0; j < 2; j++)
#pragma unroll
        for (int e = 0; e < 4; e++) s[i][j][e] = 0.0f;

#pragma unroll
    for (int kc = 0; kc < 8; kc++) {
      uint32_t ah[2][4], al[2][4], bh[2][2], bl[2][2];
#pragma unroll
      for (int i = 0; i < 2; i++) {
        const char* qh = smem + SM_QHI + (wm*32 + i*16 + g) * QSTR + (kc*16 + 2*c) * 2;
        ah[i][0] = lds32(qh);      ah[i][1] = lds32(qh + 8*QSTR);
        ah[i][2] = lds32(qh + 16); ah[i][3] = lds32(qh + 8*QSTR + 16);
        const char* ql = smem + SM_QLO + (wm*32 + i*16 + g) * QSTR + (kc*16 + 2*c) * 2;
        al[i][0] = lds32(ql);      al[i][1] = lds32(ql + 8*QSTR);
        al[i][2] = lds32(ql + 16); al[i][3] = lds32(ql + 8*QSTR + 16);
      }
#pragma unroll
      for (int j = 0; j < 2; j++) {
        const char* kh = smem + SM_KHI + (wn*16 + j*8 + g) * KSTR + (kc*16 + 2*c) * 2;
        bh[j][0] = lds32(kh); bh[j][1] = lds32(kh + 16);
        const char* kl = smem + SM_KLO + (wn*16 + j*8 + g) * KSTR + (kc*16 + 2*c) * 2;
        bl[j][0] = lds32(kl); bl[j][1] = lds32(kl + 16);
      }
      // term-major: 4 independent accumulators between same-acc writes
#pragma unroll
      for (int j = 0; j < 2; j++)
#pragma unroll
        for (int i = 0; i < 2; i++) MMA16816(s[i][j], ah[i], bh[j][0], bh[j][1]);
#pragma unroll
      for (int j = 0; j < 2; j++)
#pragma unroll
        for (int i = 0; i < 2; i++) MMA16816(s[i][j], ah[i], bl[j][0], bl[j][1]);
#pragma unroll
      for (int j = 0; j < 2; j++)
#pragma unroll
        for (int i = 0; i < 2; i++) MMA16816(s[i][j], al[i], bh[j][0], bh[j][1]);
    }

    // --- Epilogue: p = exp(s*gate); rowsum; P hi/lo -> SMEM; attn STG ---
#pragma unroll
    for (int i = 0; i < 2; i++) {
      const int lr = wm*32 + i*16 + g;
#pragma unroll
      for (int j = 0; j < 2; j++) {
        const int lc = wn*16 + j*8 + 2*c;
        float2 gt = *(const float2*)(smem + SM_GATE + (size_t)(k0 + lc) * 4);
        float p00 = __expf(s[i][j][0] * gt.x);
        float p01 = __expf(s[i][j][1] * gt.y);
        float p10 = __expf(s[i][j][2] * gt.x);
        float p11 = __expf(s[i][j][3] * gt.y);
        rs[i][0] += p00 + p01;
        rs[i][1] += p10 + p11;
        __nv_bfloat16 h00,l00,h01,l01,h10,l10,h11,l11;
        splitf(p00,h00,l00); splitf(p01,h01,l01);
        splitf(p10,h10,l10); splitf(p11,h11,l11);
        int po = lr * PSTR + lc * 2;
        *(uint32_t*)(smem + SM_PHI + po)          = pk2(h00,h01);
        *(uint32_t*)(smem + SM_PHI + po + 8*PSTR) = pk2(h10,h11);
        *(uint32_t*)(smem + SM_PLO + po)          = pk2(l00,l01);
        *(uint32_t*)(smem + SM_PLO + po + 8*PSTR) = pk2(l10,l11);
        if (write_attn) {
          float* a0 = attn + ((size_t)(b * NQS + q0 + lr)) * NKS + (k0 + lc);
          *(float2*)a0 = make_float2(p00, p01);
          *(float2*)(a0 + (size_t)8 * NKS) = make_float2(p10, p11);
        }
      }
    }
    __syncthreads();   // P visible to all warps

    // --- O += P V  (warp tile 32q x 32dh, 64 keys, 3-term, term-major) ---
#pragma unroll
    for (int kc = 0; kc < 4; kc++) {
      uint32_t ph_[2][4], pl_[2][4], vh[4][2], vl[4][2];
#pragma unroll
      for (int i = 0; i < 2; i++) {
        const char* pph = smem + SM_PHI + (wm*32 + i*16 + g) * PSTR + (kc*16 + 2*c) * 2;
        ph_[i][0] = lds32(pph);      ph_[i][1] = lds32(pph + 8*PSTR);
        ph_[i][2] = lds32(pph + 16); ph_[i][3] = lds32(pph + 8*PSTR + 16);
        const char* ppl = smem + SM_PLO + (wm*32 + i*16 + g) * PSTR + (kc*16 + 2*c) * 2;
        pl_[i][0] = lds32(ppl);      pl_[i][1] = lds32(ppl + 8*PSTR);
        pl_[i][2] = lds32(ppl + 16); pl_[i][3] = lds32(ppl + 8*PSTR + 16);
      }
#pragma unroll
      for (int j = 0; j < 4; j++) {
        const char* vhp = smem + SM_VTHI + (wn*32 + j*8 + g) * VSTR + (kc*16 + 2*c) * 2;
        vh[j][0] = lds32(vhp); vh[j][1] = lds32(vhp + 16);
        const char* vlp = smem + SM_VTLO + (wn*32 + j*8 + g) * VSTR + (kc*16 + 2*c) * 2;
        vl[j][0] = lds32(vlp); vl[j][1] = lds32(vlp + 16);
      }
      // term-major: 8 independent accumulators between same-acc writes
#pragma unroll
      for (int j = 0; j < 4; j++)
#pragma unroll
        for (int i = 0; i < 2; i++) MMA16816(o[i][j], ph_[i], vh[j][0], vh[j][1]);
#pragma unroll
      for (int j = 0; j < 4; j++)
#pragma unroll
        for (int i = 0; i < 2; i++) MMA16816(o[i][j], ph_[i], vl[j][0], vl[j][1]);
#pragma unroll
      for (int j = 0; j < 4; j++)
#pragma unroll
        for (int i = 0; i < 2; i++) MMA16816(o[i][j], pl_[i], vh[j][0], vh[j][1]);
    }
  }

  // --- Rowsum: quad shfl -> per-wn partials -> deterministic 4-way combine ---
#pragma unroll
  for (int i = 0; i < 2; i++)
#pragma unroll
    for (int h = 0; h < 2; h++) {
      float v = rs[i][h];
      v += __shfl_xor_sync(0xffffffffu, v, 1);
      v += __shfl_xor_sync(0xffffffffu, v, 2);
      rs[i][h] = v;
    }
  if (c == 0) {
#pragma unroll
    for (int i = 0; i < 2; i++)
#pragma unroll
      for (int h = 0; h < 2; h++)
        rsp[wn * 128 + wm*32 + i*16 + h*8 + g] = rs[i][h];
  }
  __syncthreads();
  if (tid < 128) {
    float rsum = (rsp[tid] + rsp[128 + tid]) + (rsp[256 + tid] + rsp[384 + tid]);
    float inv = 1.0f / rsum;
    g_inv_l[(size_t)b * NQS + q0 + tid] = inv;
    rsbuf[tid] = inv;
  }
  __syncthreads();

  // --- Normalized output store (each warp: 32q x 32dh) ---
#pragma unroll
  for (int i = 0; i < 2; i++) {
    const int lr = wm*32 + i*16 + g;
    const float inv0 = rsbuf[lr];
    const float inv1 = rsbuf[lr + 8];
    float* o0 = out + ((size_t)(b * NQS + q0 + lr)) * DHD + wn*32 + 2*c;
#pragma unroll
    for (int j = 0; j < 4; j++) {
      *(float2*)(o0 + j*8) = make_float2(o[i][j][0] * inv0, o[i][j][1] * inv0);
      *(float2*)(o0 + (size_t)8 * DHD + j*8) =
          make_float2(o[i][j][2] * inv1, o[i][j][3] * inv1);
    }
  }
}

// ---------------------------------------------------------------------------
// Normalize pass: attention[b,q,k] *= 1/rowsum[b,q]
// ---------------------------------------------------------------------------
__global__ void gpa_norm_kernel(float* __restrict__ attn) {
  const size_t n4 = (size_t)ATTN_ELEMS / 4;
  const size_t stride = (size_t)gridDim.x * blockDim.x;
  float4* a = (float4*)attn;
  for (size_t j = (size_t)blockIdx.x * blockDim.x + threadIdx.x; j < n4; j += stride) {
    float inv = g_inv_l[j >> 9];   // 512 float4 per 2048-wide row
    float4 v = a[j];
    v.x *= inv; v.y *= inv; v.z *= inv; v.w *= inv;
    a[j] = v;
  }
}

// ---------------------------------------------------------------------------
// Launch
// ---------------------------------------------------------------------------
extern "C" void kernel_launch(void* const* d_in, const int* in_sizes, int n_in,
                              void* d_out, int out_size) {
  const float* Q  = (const float*)d_in[0];
  const float* K  = (const float*)d_in[1];
  const float* V  = (const float*)d_in[2];
  const float* ph = (const float*)d_in[3];
  float* out = (float*)d_out;

  const bool write_attn = ((long long)out_size >= (long long)OUT_ELEMS + ATTN_ELEMS);
  float* attn = out + OUT_ELEMS;

  cudaFuncSetAttribute(gpa_main_kernel,
                       cudaFuncAttributeMaxDynamicSharedMemorySize, SMEM_TOTAL);

  dim3 grid(NQS / 128, BB);
  gpa_main_kernel<<<grid, NTHR, SMEM_TOTAL>>>(Q, K, V, ph, out, attn,
                                              write_attn ? 1 : 0);
  if (write_attn) {
    gpa_norm_kernel<<<4096, 256>>>(attn);
  }
}

// round 9
// speedup vs baseline: 2.6782x; 1.6979x over previous
#include <cuda_runtime.h>
#include <cuda_bf16.h>
#include <cstdint>

// ---------------------------------------------------------------------------
// Problem constants
// ---------------------------------------------------------------------------
#define BB 16
#define NQS 2048
#define NKS 2048
#define DHD 128
#define OUT_ELEMS (BB * NQS * DHD)                 // 4194304
#define ATTN_ELEMS ((long long)BB * NQS * NKS)     // 67108864

#define TWO_PI_F  6.283185307179586f
#define INV2W2_F  0.8105694691387022f   // 1/(2*(pi/4)^2)
#define SCALE_F   0.08838834764831843f  // 1/sqrt(128)

#define NTHR 512

// ---------------------------------------------------------------------------
// SMEM layout. All tile strides are 16B-aligned and ≡ 4 words (mod 32 banks)
// => every 8-lane ldmatrix phase covers all 32 banks exactly (conflict-free).
// ---------------------------------------------------------------------------
#define SM_GATE  0         // 2048 f32                              8192 B
#define SM_RS    8192      // 128 f32 (inv rowsum)                   512 B
#define SM_RSP   8704      // 4 x 128 f32 partials                  2048 B
#define SM_QHI   10752     // 128 x 136 bf16 (QSTR=272)            34816 B
#define SM_QLO   45568
#define SM_KHI   80384     // 64 x 136 bf16 (KSTR=272)             17408 B
#define SM_KLO   97792
#define SM_VHI   115200    // 64 x 136 bf16 straight [key][dh]     17408 B
#define SM_VLO   132608
#define SM_PHI   150016    // 128 x 72 bf16 (PSTR=144)             18432 B
#define SM_PLO   168448
#define SMEM_TOTAL 186880

#define QSTR 272
#define KSTR 272
#define VSTR 272
#define PSTR 144

__device__ float g_inv_l[BB * NQS];

// ---------------------------------------------------------------------------
// mma.sync m16n8k16 bf16 (row.col), D = A*B + D  — valid on plain sm_103
// ---------------------------------------------------------------------------
#define MMA16816(d, a, b0_, b1_) \
  asm volatile("mma.sync.aligned.m16n8k16.row.col.f32.bf16.bf16.f32 " \
    "{%0,%1,%2,%3}, {%4,%5,%6,%7}, {%8,%9}, {%0,%1,%2,%3};" \
    : "+f"((d)[0]), "+f"((d)[1]), "+f"((d)[2]), "+f"((d)[3]) \
    : "r"((a)[0]), "r"((a)[1]), "r"((a)[2]), "r"((a)[3]), "r"(b0_), "r"(b1_))

#define LDSM_X4(R, ADDR) \
  asm volatile("ldmatrix.sync.aligned.m8n8.x4.shared.b16 {%0,%1,%2,%3}, [%4];" \
    : "=r"((R)[0]), "=r"((R)[1]), "=r"((R)[2]), "=r"((R)[3]) : "r"(ADDR))

#define LDSM_X4_T(R, ADDR) \
  asm volatile("ldmatrix.sync.aligned.m8n8.x4.trans.shared.b16 {%0,%1,%2,%3}, [%4];" \
    : "=r"((R)[0]), "=r"((R)[1]), "=r"((R)[2]), "=r"((R)[3]) : "r"(ADDR))

__device__ __forceinline__ uint32_t smem_u32(const void* p) {
  uint32_t a;
  asm("{ .reg .u64 t; cvta.to.shared.u64 t, %1; cvt.u32.u64 %0, t; }"
      : "=r"(a) : "l"(p));
  return a;
}
__device__ __forceinline__ uint32_t pk2(__nv_bfloat16 a, __nv_bfloat16 b) {
  __nv_bfloat162 t; t.x = a; t.y = b;
  return *reinterpret_cast<uint32_t*>(&t);
}
__device__ __forceinline__ void splitf(float x, __nv_bfloat16& h, __nv_bfloat16& l) {
  h = __float2bfloat16_rn(x);
  l = __float2bfloat16_rn(x - __bfloat162float(h));
}
// convert a float4 into packed hi/lo bf16x2 pairs
__device__ __forceinline__ void cvt4(float4 v, uint2& hi, uint2& lo) {
  __nv_bfloat16 hx,lx,hy,ly,hz,lz,hw,lw;
  splitf(v.x,hx,lx); splitf(v.y,hy,ly); splitf(v.z,hz,lz); splitf(v.w,hw,lw);
  hi.x = pk2(hx,hy); hi.y = pk2(hz,hw);
  lo.x = pk2(lx,ly); lo.y = pk2(lz,lw);
}

// ---------------------------------------------------------------------------
// Main kernel: one CTA per (batch, 128-q tile). 512 threads = 16 warps.
// ---------------------------------------------------------------------------
__global__ void __launch_bounds__(NTHR, 1)
gpa_main_kernel(const float* __restrict__ Q, const float* __restrict__ K,
                const float* __restrict__ V, const float* __restrict__ phases,
                float* __restrict__ out, float* __restrict__ attn,
                int write_attn) {
  extern __shared__ char smem[];
  const uint32_t sb = smem_u32(smem);
  const int tid = threadIdx.x;
  const int wid = tid >> 5;
  const int lane = tid & 31;
  const int g = lane >> 2;       // fragment row group 0..7
  const int c = lane & 3;        // fragment col group 0..3
  const int wm = wid >> 2;       // 0..3 : 32-q-row band
  const int wn = wid & 3;        // 0..3 : QK key stripe / PV dh stripe
  const int m = lane >> 3;       // ldmatrix matrix index 0..3
  const int rr = lane & 7;       // ldmatrix row within matrix

  const int b = blockIdx.y;
  const int q0 = blockIdx.x * 128;
  const float* Qb = Q + ((size_t)b * NQS + q0) * DHD;
  const float* Kb = K + (size_t)b * NKS * DHD;
  const float* Vb = V + (size_t)b * NKS * DHD;

  float* gate_s = (float*)(smem + SM_GATE);
  float* rsbuf  = (float*)(smem + SM_RS);
  float* rsp    = (float*)(smem + SM_RSP);

  // ldmatrix lane addresses (per-warp constant bases)
  // A fragments (Q / P): matrices ordered (row0-7), (row+8), (col+8), (both)
  const uint32_t aQ0 = sb + SM_QHI + (uint32_t)(wm*32 + (m&1)*8 + rr) * QSTR + (m>>1)*16;
  const uint32_t aQ1 = aQ0 + 16 * QSTR;
  const uint32_t dQLO = SM_QLO - SM_QHI;
  // B fragments (K): matrices ordered (n0-7,k0-7),(n0-7,k+8),(n+8,k0-7),(n+8,k+8)
  const uint32_t bK = sb + SM_KHI + (uint32_t)(wn*16 + (m>>1)*8 + rr) * KSTR + (m&1)*16;
  const uint32_t dKLO = SM_KLO - SM_KHI;
  const uint32_t aP0 = sb + SM_PHI + (uint32_t)(wm*32 + (m&1)*8 + rr) * PSTR + (m>>1)*16;
  const uint32_t aP1 = aP0 + 16 * PSTR;
  const uint32_t dPLO = SM_PLO - SM_PHI;
  // B fragments (V via trans): memory rows = key(k), cols = dh(n).
  // matrices: (k0-7,n0-7),(k+8,n0-7),(k0-7,n+8),(k+8,n+8)
  const uint32_t vB0 = sb + SM_VHI + (uint32_t)((m&1)*8 + rr) * VSTR
                       + (uint32_t)(wn*64) + (m>>1)*16;
  const uint32_t vB1 = vB0 + 32;
  const uint32_t dVLO = SM_VLO - SM_VHI;

  // --- gate precompute (includes 1/sqrt(dh)) ---
  for (int k = tid; k < NKS; k += NTHR) {
    float ph = phases[k];
    float pd = fminf(ph, TWO_PI_F - ph);
    gate_s[k] = __expf(-pd * pd * INV2W2_F) * SCALE_F;
  }

  // --- prefetch first K/V tile into registers ---
  const float4* kp4 = (const float4*)Kb;
  const float4* vp4 = (const float4*)Vb;
  float4 pfk[4], pfv[4];
#pragma unroll
  for (int t = 0; t < 4; t++) {
    pfk[t] = kp4[tid + t * NTHR];
    pfv[t] = vp4[tid + t * NTHR];
  }

  // --- Q tile -> SMEM bf16 hi/lo (128 x 128) ---
  {
    const float4* qp = (const float4*)Qb;
    for (int it = tid; it < 4096; it += NTHR) {
      int row = it >> 5;
      int c4 = (it & 31) << 2;
      float4 v = qp[it];
      uint2 hi, lo;
      cvt4(v, hi, lo);
      int off = row * QSTR + c4 * 2;
      *(uint2*)(smem + SM_QHI + off) = hi;
      *(uint2*)(smem + SM_QLO + off) = lo;
    }
  }

  float o[2][4][4];   // persistent O accumulators: 32 q x 32 dh per warp
#pragma unroll
  for (int i = 0; i < 2; i++)
#pragma unroll
    for (int j = 0; j < 4; j++)
#pragma unroll
      for (int e = 0; e < 4; e++) o[i][j][e] = 0.0f;

  float rs[2][2] = {{0.f,0.f},{0.f,0.f}};

  for (int kt = 0; kt < 32; kt++) {
    const int k0 = kt * 64;

    // --- store prefetched K/V tile (converted hi/lo) into SMEM ---
#pragma unroll
    for (int t = 0; t < 4; t++) {
      int it = tid + t * NTHR;
      int row = it >> 5;
      int c4 = (it & 31) << 2;
      int off = row * KSTR + c4 * 2;   // KSTR == VSTR
      uint2 hi, lo;
      cvt4(pfk[t], hi, lo);
      *(uint2*)(smem + SM_KHI + off) = hi;
      *(uint2*)(smem + SM_KLO + off) = lo;
      cvt4(pfv[t], hi, lo);
      *(uint2*)(smem + SM_VHI + off) = hi;
      *(uint2*)(smem + SM_VLO + off) = lo;
    }
    __syncthreads();

    // --- issue next tile's LDG (hidden behind QK + epilogue + PV) ---
    if (kt < 31) {
      int base = (kt + 1) * 2048;
#pragma unroll
      for (int t = 0; t < 4; t++) {
        pfk[t] = kp4[base + tid + t * NTHR];
        pfv[t] = vp4[base + tid + t * NTHR];
      }
    }

    // --- S = Q K^T  (warp tile 32q x 16k, 3-term hi/lo, term-major) ---
    float s[2][2][4];
#pragma unroll
    for (int i = 0; i < 2; i++)
#pragma unroll
      for (int j = 0; j < 2; j++)
#pragma unroll
        for (int e = 0; e < 4; e++) s[i][j][e] = 0.0f;

#pragma unroll
    for (int kc = 0; kc < 8; kc++) {
      uint32_t ah0[4], ah1[4], al0[4], al1[4], bh[4], bl[4];
      const uint32_t ko = kc * 32;
      LDSM_X4(ah0, aQ0 + ko);
      LDSM_X4(ah1, aQ1 + ko);
      LDSM_X4(al0, aQ0 + dQLO + ko);
      LDSM_X4(al1, aQ1 + dQLO + ko);
      LDSM_X4(bh, bK + ko);
      LDSM_X4(bl, bK + dKLO + ko);
      // term-major: 4 independent accumulators between same-acc writes
      MMA16816(s[0][0], ah0, bh[0], bh[1]);
      MMA16816(s[1][0], ah1, bh[0], bh[1]);
      MMA16816(s[0][1], ah0, bh[2], bh[3]);
      MMA16816(s[1][1], ah1, bh[2], bh[3]);
      MMA16816(s[0][0], ah0, bl[0], bl[1]);
      MMA16816(s[1][0], ah1, bl[0], bl[1]);
      MMA16816(s[0][1], ah0, bl[2], bl[3]);
      MMA16816(s[1][1], ah1, bl[2], bl[3]);
      MMA16816(s[0][0], al0, bh[0], bh[1]);
      MMA16816(s[1][0], al1, bh[0], bh[1]);
      MMA16816(s[0][1], al0, bh[2], bh[3]);
      MMA16816(s[1][1], al1, bh[2], bh[3]);
    }

    // --- Epilogue: p = exp(s*gate); rowsum; P hi/lo -> SMEM; attn STG ---
#pragma unroll
    for (int i = 0; i < 2; i++) {
      const int lr = wm*32 + i*16 + g;
#pragma unroll
      for (int j = 0; j < 2; j++) {
        const int lc = wn*16 + j*8 + 2*c;
        float2 gt = *(const float2*)(smem + SM_GATE + (size_t)(k0 + lc) * 4);
        float p00 = __expf(s[i][j][0] * gt.x);
        float p01 = __expf(s[i][j][1] * gt.y);
        float p10 = __expf(s[i][j][2] * gt.x);
        float p11 = __expf(s[i][j][3] * gt.y);
        rs[i][0] += p00 + p01;
        rs[i][1] += p10 + p11;
        __nv_bfloat16 h00,l00,h01,l01,h10,l10,h11,l11;
        splitf(p00,h00,l00); splitf(p01,h01,l01);
        splitf(p10,h10,l10); splitf(p11,h11,l11);
        int po = lr * PSTR + lc * 2;
        *(uint32_t*)(smem + SM_PHI + po)          = pk2(h00,h01);
        *(uint32_t*)(smem + SM_PHI + po + 8*PSTR) = pk2(h10,h11);
        *(uint32_t*)(smem + SM_PLO + po)          = pk2(l00,l01);
        *(uint32_t*)(smem + SM_PLO + po + 8*PSTR) = pk2(l10,l11);
        if (write_attn) {
          float* a0 = attn + ((size_t)(b * NQS + q0 + lr)) * NKS + (k0 + lc);
          *(float2*)a0 = make_float2(p00, p01);
          *(float2*)(a0 + (size_t)8 * NKS) = make_float2(p10, p11);
        }
      }
    }
    __syncthreads();   // P visible to all warps

    // --- O += P V  (warp tile 32q x 32dh, 64 keys, 3-term, term-major) ---
#pragma unroll
    for (int kc = 0; kc < 4; kc++) {
      uint32_t ph0[4], ph1[4], pl0[4], pl1[4], vh[8], vl[8];
      const uint32_t po = kc * 32;
      const uint32_t vo = kc * 16 * VSTR;
      LDSM_X4(ph0, aP0 + po);
      LDSM_X4(ph1, aP1 + po);
      LDSM_X4(pl0, aP0 + dPLO + po);
      LDSM_X4(pl1, aP1 + dPLO + po);
      LDSM_X4_T(vh,     vB0 + vo);
      LDSM_X4_T(vh + 4, vB1 + vo);
      LDSM_X4_T(vl,     vB0 + dVLO + vo);
      LDSM_X4_T(vl + 4, vB1 + dVLO + vo);
      // term-major: 8 independent accumulators between same-acc writes
#pragma unroll
      for (int j = 0; j < 4; j++) {
        MMA16816(o[0][j], ph0, vh[2*j], vh[2*j+1]);
        MMA16816(o[1][j], ph1, vh[2*j], vh[2*j+1]);
      }
#pragma unroll
      for (int j = 0; j < 4; j++) {
        MMA16816(o[0][j], ph0, vl[2*j], vl[2*j+1]);
        MMA16816(o[1][j], ph1, vl[2*j], vl[2*j+1]);
      }
#pragma unroll
      for (int j = 0; j < 4; j++) {
        MMA16816(o[0][j], pl0, vh[2*j], vh[2*j+1]);
        MMA16816(o[1][j], pl1, vh[2*j], vh[2*j+1]);
      }
    }
    __syncthreads();   // K/V/P consumed; safe to overwrite next iteration
  }

  // --- Rowsum: quad shfl -> per-wn partials -> deterministic 4-way combine ---
#pragma unroll
  for (int i = 0; i < 2; i++)
#pragma unroll
    for (int h = 0; h < 2; h++) {
      float v = rs[i][h];
      v += __shfl_xor_sync(0xffffffffu, v, 1);
      v += __shfl_xor_sync(0xffffffffu, v, 2);
      rs[i][h] = v;
    }
  if (c == 0) {
#pragma unroll
    for (int i = 0; i < 2; i++)
#pragma unroll
      for (int h = 0; h < 2; h++)
        rsp[wn * 128 + wm*32 + i*16 + h*8 + g] = rs[i][h];
  }
  __syncthreads();
  if (tid < 128) {
    float rsum = (rsp[tid] + rsp[128 + tid]) + (rsp[256 + tid] + rsp[384 + tid]);
    float inv = 1.0f / rsum;
    g_inv_l[(size_t)b * NQS + q0 + tid] = inv;
    rsbuf[tid] = inv;
  }
  __syncthreads();

  // --- Normalized output store (each warp: 32q x 32dh) ---
#pragma unroll
  for (int i = 0; i < 2; i++) {
    const int lr = wm*32 + i*16 + g;
    const float inv0 = rsbuf[lr];
    const float inv1 = rsbuf[lr + 8];
    float* o0 = out + ((size_t)(b * NQS + q0 + lr)) * DHD + wn*32 + 2*c;
#pragma unroll
    for (int j = 0; j < 4; j++) {
      *(float2*)(o0 + j*8) = make_float2(o[i][j][0] * inv0, o[i][j][1] * inv0);
      *(float2*)(o0 + (size_t)8 * DHD + j*8) =
          make_float2(o[i][j][2] * inv1, o[i][j][3] * inv1);
    }
  }
}

// ---------------------------------------------------------------------------
// Normalize pass: attention[b,q,k] *= 1/rowsum[b,q]
// ---------------------------------------------------------------------------
__global__ void gpa_norm_kernel(float* __restrict__ attn) {
  const size_t n4 = (size_t)ATTN_ELEMS / 4;
  const size_t stride = (size_t)gridDim.x * blockDim.x;
  float4* a = (float4*)attn;
  for (size_t j = (size_t)blockIdx.x * blockDim.x + threadIdx.x; j < n4; j += stride) {
    float inv = g_inv_l[j >> 9];   // 512 float4 per 2048-wide row
    float4 v = a[j];
    v.x *= inv; v.y *= inv; v.z *= inv; v.w *= inv;
    a[j] = v;
  }
}

// ---------------------------------------------------------------------------
// Launch
// ---------------------------------------------------------------------------
extern "C" void kernel_launch(void* const* d_in, const int* in_sizes, int n_in,
                              void* d_out, int out_size) {
  const float* Q  = (const float*)d_in[0];
  const float* K  = (const float*)d_in[1];
  const float* V  = (const float*)d_in[2];
  const float* ph = (const float*)d_in[3];
  float* out = (float*)d_out;

  const bool write_attn = ((long long)out_size >= (long long)OUT_ELEMS + ATTN_ELEMS);
  float* attn = out + OUT_ELEMS;

  cudaFuncSetAttribute(gpa_main_kernel,
                       cudaFuncAttributeMaxDynamicSharedMemorySize, SMEM_TOTAL);

  dim3 grid(NQS / 128, BB);
  gpa_main_kernel<<<grid, NTHR, SMEM_TOTAL>>>(Q, K, V, ph, out, attn,
                                              write_attn ? 1 : 0);
  if (write_attn) {
    gpa_norm_kernel<<<4096, 256>>>(attn);
  }
}

// round 13
// speedup vs baseline: 4.1901x; 1.5645x over previous
#include <cuda_runtime.h>
#include <cuda_fp16.h>
#include <cstdint>

// ---------------------------------------------------------------------------
// Problem constants
// ---------------------------------------------------------------------------
#define BB 16
#define NQS 2048
#define NKS 2048
#define DHD 128
#define OUT_ELEMS (BB * NQS * DHD)                 // 4194304
#define ATTN_ELEMS ((long long)BB * NQS * NKS)     // 67108864

#define TWO_PI_F  6.283185307179586f
#define INV2W2_F  0.8105694691387022f   // 1/(2*(pi/4)^2)
#define SCALE_F   0.08838834764831843f  // 1/sqrt(128)

#define NTHR 512

// ---------------------------------------------------------------------------
// SMEM layout. All tile strides are 16B-aligned and ≡ 16 bytes mod 128
// => every 8-row ldmatrix phase covers all 32 banks exactly (conflict-free,
// proven in R8). fp16 single tiles; K/V double-buffered.
// ---------------------------------------------------------------------------
#define SM_GATE  0         // 2048 f32                              8192 B
#define SM_RS    8192      // 128 f32 (inv rowsum)                   512 B
#define SM_RSP   8704      // 4 x 128 f32 partials                  2048 B
#define SM_Q     10752     // 128 x 136 fp16 (QSTR=272)            34816 B
#define SM_K0    45568     // 2 x (64 x 136 fp16)                  34816 B
#define SM_V0    80384     // 2 x (64 x 136 fp16) straight [key][dh]
#define SM_P     115200    // 128 x 72 fp16 (PSTR=144)             18432 B
#define SMEM_TOTAL 133632

#define QSTR 272
#define KSTR 272
#define VSTR 272
#define PSTR 144
#define KVBUF 17408

__device__ float g_inv_l[BB * NQS];

// ---------------------------------------------------------------------------
// mma.sync m16n8k16 fp16 (row.col), fp32 accum — valid on plain sm_103
// ---------------------------------------------------------------------------
#define MMA16816(d, a, b0_, b1_) \
  asm volatile("mma.sync.aligned.m16n8k16.row.col.f32.f16.f16.f32 " \
    "{%0,%1,%2,%3}, {%4,%5,%6,%7}, {%8,%9}, {%0,%1,%2,%3};" \
    : "+f"((d)[0]), "+f"((d)[1]), "+f"((d)[2]), "+f"((d)[3]) \
    : "r"((a)[0]), "r"((a)[1]), "r"((a)[2]), "r"((a)[3]), "r"(b0_), "r"(b1_))

#define LDSM_X4(R, ADDR) \
  asm volatile("ldmatrix.sync.aligned.m8n8.x4.shared.b16 {%0,%1,%2,%3}, [%4];" \
    : "=r"((R)[0]), "=r"((R)[1]), "=r"((R)[2]), "=r"((R)[3]) : "r"(ADDR))

#define LDSM_X4_T(R, ADDR) \
  asm volatile("ldmatrix.sync.aligned.m8n8.x4.trans.shared.b16 {%0,%1,%2,%3}, [%4];" \
    : "=r"((R)[0]), "=r"((R)[1]), "=r"((R)[2]), "=r"((R)[3]) : "r"(ADDR))

__device__ __forceinline__ uint32_t smem_u32(const void* p) {
  uint32_t a;
  asm("{ .reg .u64 t; cvta.to.shared.u64 t, %1; cvt.u32.u64 %0, t; }"
      : "=r"(a) : "l"(p));
  return a;
}
__device__ __forceinline__ uint32_t pkh2(float a, float b) {
  __half2 t = __floats2half2_rn(a, b);
  return *reinterpret_cast<uint32_t*>(&t);
}
// convert a float4 into two packed fp16x2 words
__device__ __forceinline__ uint2 cvt4h(float4 v) {
  uint2 r;
  r.x = pkh2(v.x, v.y);
  r.y = pkh2(v.z, v.w);
  return r;
}

// ---------------------------------------------------------------------------
// Main kernel: one CTA per (batch, 128-q tile). 512 threads = 16 warps.
// ---------------------------------------------------------------------------
__global__ void __launch_bounds__(NTHR, 1)
gpa_main_kernel(const float* __restrict__ Q, const float* __restrict__ K,
                const float* __restrict__ V, const float* __restrict__ phases,
                float* __restrict__ out, float* __restrict__ attn,
                int write_attn) {
  extern __shared__ char smem[];
  const uint32_t sb = smem_u32(smem);
  const int tid = threadIdx.x;
  const int wid = tid >> 5;
  const int lane = tid & 31;
  const int g = lane >> 2;       // fragment row group 0..7
  const int c = lane & 3;        // fragment col group 0..3
  const int wm = wid >> 2;       // 0..3 : 32-q-row band
  const int wn = wid & 3;        // 0..3 : QK key stripe / PV dh stripe
  const int m = lane >> 3;       // ldmatrix matrix index 0..3
  const int rr = lane & 7;       // ldmatrix row within matrix

  const int b = blockIdx.y;
  const int q0 = blockIdx.x * 128;
  const float* Qb = Q + ((size_t)b * NQS + q0) * DHD;
  const float* Kb = K + (size_t)b * NKS * DHD;
  const float* Vb = V + (size_t)b * NKS * DHD;

  float* gate_s = (float*)(smem + SM_GATE);
  float* rsbuf  = (float*)(smem + SM_RS);
  float* rsp    = (float*)(smem + SM_RSP);

  // ldmatrix lane addresses (per-warp constant bases) — layouts proven in R8
  const uint32_t aQ0 = sb + SM_Q + (uint32_t)(wm*32 + (m&1)*8 + rr) * QSTR + (m>>1)*16;
  const uint32_t aQ1 = aQ0 + 16 * QSTR;
  const uint32_t bKb = sb + SM_K0 + (uint32_t)(wn*16 + (m>>1)*8 + rr) * KSTR + (m&1)*16;
  const uint32_t aP0 = sb + SM_P + (uint32_t)(wm*32 + (m&1)*8 + rr) * PSTR + (m>>1)*16;
  const uint32_t aP1 = aP0 + 16 * PSTR;
  const uint32_t vBb = sb + SM_V0 + (uint32_t)((m&1)*8 + rr) * VSTR
                       + (uint32_t)(wn*64) + (m>>1)*16;

  // --- gate precompute (includes 1/sqrt(dh)) ---
  for (int k = tid; k < NKS; k += NTHR) {
    float ph = phases[k];
    float pd = fminf(ph, TWO_PI_F - ph);
    gate_s[k] = __expf(-pd * pd * INV2W2_F) * SCALE_F;
  }

  // --- prefetch first K/V tile into registers ---
  const float4* kp4 = (const float4*)Kb;
  const float4* vp4 = (const float4*)Vb;
  float4 pfk[4], pfv[4];
#pragma unroll
  for (int t = 0; t < 4; t++) {
    pfk[t] = kp4[tid + t * NTHR];
    pfv[t] = vp4[tid + t * NTHR];
  }

  // --- Q tile -> SMEM fp16 (128 x 128) ---
  {
    const float4* qp = (const float4*)Qb;
    for (int it = tid; it < 4096; it += NTHR) {
      int row = it >> 5;
      int c4 = (it & 31) << 2;
      *(uint2*)(smem + SM_Q + row * QSTR + c4 * 2) = cvt4h(qp[it]);
    }
  }

  // --- store tile 0 into K/V buffer 0 ---
#pragma unroll
  for (int t = 0; t < 4; t++) {
    int it = tid + t * NTHR;
    int row = it >> 5;
    int c4 = (it & 31) << 2;
    int off = row * KSTR + c4 * 2;
    *(uint2*)(smem + SM_K0 + off) = cvt4h(pfk[t]);
    *(uint2*)(smem + SM_V0 + off) = cvt4h(pfv[t]);
  }
  __syncthreads();

  float o[2][4][4];   // persistent O accumulators: 32 q x 32 dh per warp
#pragma unroll
  for (int i = 0; i < 2; i++)
#pragma unroll
    for (int j = 0; j < 4; j++)
#pragma unroll
      for (int e = 0; e < 4; e++) o[i][j][e] = 0.0f;

  float rs[2][2] = {{0.f,0.f},{0.f,0.f}};

  for (int kt = 0; kt < 32; kt++) {
    const int k0 = kt * 64;
    const uint32_t bufo = (uint32_t)(kt & 1) * KVBUF;

    // --- issue next tile's LDG (hidden behind QK + epilogue + PV) ---
    if (kt < 31) {
      int base = (kt + 1) * 2048;
#pragma unroll
      for (int t = 0; t < 4; t++) {
        pfk[t] = kp4[base + tid + t * NTHR];
        pfv[t] = vp4[base + tid + t * NTHR];
      }
    }

    // --- S = Q K^T  (warp tile 32q x 16k, single-pass fp16) ---
    float s[2][2][4];
#pragma unroll
    for (int i = 0; i < 2; i++)
#pragma unroll
      for (int j = 0; j < 2; j++)
#pragma unroll
        for (int e = 0; e < 4; e++) s[i][j][e] = 0.0f;

#pragma unroll
    for (int kc = 0; kc < 8; kc++) {
      uint32_t a0[4], a1[4], bk[4];
      const uint32_t ko = kc * 32;
      LDSM_X4(a0, aQ0 + ko);
      LDSM_X4(a1, aQ1 + ko);
      LDSM_X4(bk, bKb + bufo + ko);
      MMA16816(s[0][0], a0, bk[0], bk[1]);
      MMA16816(s[1][0], a1, bk[0], bk[1]);
      MMA16816(s[0][1], a0, bk[2], bk[3]);
      MMA16816(s[1][1], a1, bk[2], bk[3]);
    }

    // --- Epilogue: p = exp(s*gate); rowsum; P fp16 -> SMEM; attn STG ---
#pragma unroll
    for (int i = 0; i < 2; i++) {
      const int lr = wm*32 + i*16 + g;
#pragma unroll
      for (int j = 0; j < 2; j++) {
        const int lc = wn*16 + j*8 + 2*c;
        float2 gt = *(const float2*)(smem + SM_GATE + (size_t)(k0 + lc) * 4);
        float p00 = __expf(s[i][j][0] * gt.x);
        float p01 = __expf(s[i][j][1] * gt.y);
        float p10 = __expf(s[i][j][2] * gt.x);
        float p11 = __expf(s[i][j][3] * gt.y);
        rs[i][0] += p00 + p01;
        rs[i][1] += p10 + p11;
        int po = lr * PSTR + lc * 2;
        *(uint32_t*)(smem + SM_P + po)          = pkh2(p00, p01);
        *(uint32_t*)(smem + SM_P + po + 8*PSTR) = pkh2(p10, p11);
        if (write_attn) {
          float* a0 = attn + ((size_t)(b * NQS + q0 + lr)) * NKS + (k0 + lc);
          *(float2*)a0 = make_float2(p00, p01);
          *(float2*)(a0 + (size_t)8 * NKS) = make_float2(p10, p11);
        }
      }
    }
    __syncthreads();   // P visible to all warps

    // --- store next K/V tile into the other buffer (overlaps PV) ---
    if (kt < 31) {
      const uint32_t nb = (uint32_t)((kt + 1) & 1) * KVBUF;
#pragma unroll
      for (int t = 0; t < 4; t++) {
        int it = tid + t * NTHR;
        int row = it >> 5;
        int c4 = (it & 31) << 2;
        int off = row * KSTR + c4 * 2;
        *(uint2*)(smem + SM_K0 + nb + off) = cvt4h(pfk[t]);
        *(uint2*)(smem + SM_V0 + nb + off) = cvt4h(pfv[t]);
      }
    }

    // --- O += P V  (warp tile 32q x 32dh, 64 keys, single-pass fp16) ---
#pragma unroll
    for (int kc = 0; kc < 4; kc++) {
      uint32_t p0[4], p1[4], v0[4], v1[4];
      const uint32_t po = kc * 32;
      const uint32_t vo = bufo + kc * 16 * VSTR;
      LDSM_X4(p0, aP0 + po);
      LDSM_X4(p1, aP1 + po);
      LDSM_X4_T(v0, vBb + vo);
      LDSM_X4_T(v1, vBb + vo + 32);
      MMA16816(o[0][0], p0, v0[0], v0[1]);
      MMA16816(o[1][0], p1, v0[0], v0[1]);
      MMA16816(o[0][1], p0, v0[2], v0[3]);
      MMA16816(o[1][1], p1, v0[2], v0[3]);
      MMA16816(o[0][2], p0, v1[0], v1[1]);
      MMA16816(o[1][2], p1, v1[0], v1[1]);
      MMA16816(o[0][3], p0, v1[2], v1[3]);
      MMA16816(o[1][3], p1, v1[2], v1[3]);
    }
    __syncthreads();   // K/V/P consumed; next iteration may overwrite
  }

  // --- Rowsum: quad shfl -> per-wn partials -> deterministic 4-way combine ---
#pragma unroll
  for (int i = 0; i < 2; i++)
#pragma unroll
    for (int h = 0; h < 2; h++) {
      float v = rs[i][h];
      v += __shfl_xor_sync(0xffffffffu, v, 1);
      v += __shfl_xor_sync(0xffffffffu, v, 2);
      rs[i][h] = v;
    }
  if (c == 0) {
#pragma unroll
    for (int i = 0; i < 2; i++)
#pragma unroll
      for (int h = 0; h < 2; h++)
        rsp[wn * 128 + wm*32 + i*16 + h*8 + g] = rs[i][h];
  }
  __syncthreads();
  if (tid < 128) {
    float rsum = (rsp[tid] + rsp[128 + tid]) + (rsp[256 + tid] + rsp[384 + tid]);
    float inv = 1.0f / rsum;
    g_inv_l[(size_t)b * NQS + q0 + tid] = inv;
    rsbuf[tid] = inv;
  }
  __syncthreads();

  // --- Normalized output store (each warp: 32q x 32dh) ---
#pragma unroll
  for (int i = 0; i < 2; i++) {
    const int lr = wm*32 + i*16 + g;
    const float inv0 = rsbuf[lr];
    const float inv1 = rsbuf[lr + 8];
    float* o0 = out + ((size_t)(b * NQS + q0 + lr)) * DHD + wn*32 + 2*c;
#pragma unroll
    for (int j = 0; j < 4; j++) {
      *(float2*)(o0 + j*8) = make_float2(o[i][j][0] * inv0, o[i][j][1] * inv0);
      *(float2*)(o0 + (size_t)8 * DHD + j*8) =
          make_float2(o[i][j][2] * inv1, o[i][j][3] * inv1);
    }
  }
}

// ---------------------------------------------------------------------------
// Normalize pass: attention[b,q,k] *= 1/rowsum[b,q]
// ---------------------------------------------------------------------------
__global__ void gpa_norm_kernel(float* __restrict__ attn) {
  const size_t n4 = (size_t)ATTN_ELEMS / 4;
  const size_t stride = (size_t)gridDim.x * blockDim.x;
  float4* a = (float4*)attn;
  for (size_t j = (size_t)blockIdx.x * blockDim.x + threadIdx.x; j < n4; j += stride) {
    float inv = g_inv_l[j >> 9];   // 512 float4 per 2048-wide row
    float4 v = a[j];
    v.x *= inv; v.y *= inv; v.z *= inv; v.w *= inv;
    a[j] = v;
  }
}

// ---------------------------------------------------------------------------
// Launch
// ---------------------------------------------------------------------------
extern "C" void kernel_launch(void* const* d_in, const int* in_sizes, int n_in,
                              void* d_out, int out_size) {
  const float* Q  = (const float*)d_in[0];
  const float* K  = (const float*)d_in[1];
  const float* V  = (const float*)d_in[2];
  const float* ph = (const float*)d_in[3];
  float* out = (float*)d_out;

  const bool write_attn = ((long long)out_size >= (long long)OUT_ELEMS + ATTN_ELEMS);
  float* attn = out + OUT_ELEMS;

  cudaFuncSetAttribute(gpa_main_kernel,
                       cudaFuncAttributeMaxDynamicSharedMemorySize, SMEM_TOTAL);

  dim3 grid(NQS / 128, BB);
  gpa_main_kernel<<<grid, NTHR, SMEM_TOTAL>>>(Q, K, V, ph, out, attn,
                                              write_attn ? 1 : 0);
  if (write_attn) {
    gpa_norm_kernel<<<4096, 256>>>(attn);
  }
}

// round 14
// speedup vs baseline: 4.2214x; 1.0075x over previous
#include <cuda_runtime.h>
#include <cuda_fp16.h>
#include <cstdint>

// ---------------------------------------------------------------------------
// Problem constants
// ---------------------------------------------------------------------------
#define BB 16
#define NQS 2048
#define NKS 2048
#define DHD 128
#define OUT_ELEMS (BB * NQS * DHD)                 // 4194304
#define ATTN_ELEMS ((long long)BB * NQS * NKS)     // 67108864

#define TWO_PI_F  6.283185307179586f
#define INV2W2_F  0.8105694691387022f   // 1/(2*(pi/4)^2)
#define SCALE_F   0.08838834764831843f  // 1/sqrt(128)

#define NTHR 512

// ---------------------------------------------------------------------------
// SMEM layout. All tile strides are 16B-aligned and ≡ 16 bytes mod 128
// => every 8-row ldmatrix phase covers all 32 banks exactly (conflict-free,
// proven in R8). fp16 single tiles; K/V double-buffered.
// ---------------------------------------------------------------------------
#define SM_GATE  0         // 2048 f32                              8192 B
#define SM_RS    8192      // 128 f32 (inv rowsum)                   512 B
#define SM_RSP   8704      // 4 x 128 f32 partials                  2048 B
#define SM_Q     10752     // 128 x 136 fp16 (QSTR=272)            34816 B
#define SM_K0    45568     // 2 x (64 x 136 fp16)                  34816 B
#define SM_V0    80384     // 2 x (64 x 136 fp16) straight [key][dh]
#define SM_P     115200    // 128 x 72 fp16 (PSTR=144)             18432 B
#define SMEM_TOTAL 133632

#define QSTR 272
#define KSTR 272
#define VSTR 272
#define PSTR 144
#define KVBUF 17408

// ---------------------------------------------------------------------------
// mma.sync m16n8k16 fp16 (row.col), fp32 accum — valid on plain sm_103
// ---------------------------------------------------------------------------
#define MMA16816(d, a, b0_, b1_) \
  asm volatile("mma.sync.aligned.m16n8k16.row.col.f32.f16.f16.f32 " \
    "{%0,%1,%2,%3}, {%4,%5,%6,%7}, {%8,%9}, {%0,%1,%2,%3};" \
    : "+f"((d)[0]), "+f"((d)[1]), "+f"((d)[2]), "+f"((d)[3]) \
    : "r"((a)[0]), "r"((a)[1]), "r"((a)[2]), "r"((a)[3]), "r"(b0_), "r"(b1_))

#define LDSM_X4(R, ADDR) \
  asm volatile("ldmatrix.sync.aligned.m8n8.x4.shared.b16 {%0,%1,%2,%3}, [%4];" \
    : "=r"((R)[0]), "=r"((R)[1]), "=r"((R)[2]), "=r"((R)[3]) : "r"(ADDR))

#define LDSM_X4_T(R, ADDR) \
  asm volatile("ldmatrix.sync.aligned.m8n8.x4.trans.shared.b16 {%0,%1,%2,%3}, [%4];" \
    : "=r"((R)[0]), "=r"((R)[1]), "=r"((R)[2]), "=r"((R)[3]) : "r"(ADDR))

__device__ __forceinline__ uint32_t smem_u32(const void* p) {
  uint32_t a;
  asm("{ .reg .u64 t; cvta.to.shared.u64 t, %1; cvt.u32.u64 %0, t; }"
      : "=r"(a) : "l"(p));
  return a;
}
__device__ __forceinline__ uint32_t pkh2(float a, float b) {
  __half2 t = __floats2half2_rn(a, b);
  return *reinterpret_cast<uint32_t*>(&t);
}
// convert a float4 into two packed fp16x2 words
__device__ __forceinline__ uint2 cvt4h(float4 v) {
  uint2 r;
  r.x = pkh2(v.x, v.y);
  r.y = pkh2(v.z, v.w);
  return r;
}

// ---------------------------------------------------------------------------
// Main kernel: one CTA per (batch, 128-q tile). 512 threads = 16 warps.
// Normalization of this CTA's attention block is folded in at the end
// (self-read-modify-write, overlapped across CTAs/waves).
// ---------------------------------------------------------------------------
__global__ void __launch_bounds__(NTHR, 1)
gpa_main_kernel(const float* __restrict__ Q, const float* __restrict__ K,
                const float* __restrict__ V, const float* __restrict__ phases,
                float* __restrict__ out, float* __restrict__ attn,
                int write_attn) {
  extern __shared__ char smem[];
  const uint32_t sb = smem_u32(smem);
  const int tid = threadIdx.x;
  const int wid = tid >> 5;
  const int lane = tid & 31;
  const int g = lane >> 2;       // fragment row group 0..7
  const int c = lane & 3;        // fragment col group 0..3
  const int wm = wid >> 2;       // 0..3 : 32-q-row band
  const int wn = wid & 3;        // 0..3 : QK key stripe / PV dh stripe
  const int m = lane >> 3;       // ldmatrix matrix index 0..3
  const int rr = lane & 7;       // ldmatrix row within matrix

  const int b = blockIdx.y;
  const int q0 = blockIdx.x * 128;
  const float* Qb = Q + ((size_t)b * NQS + q0) * DHD;
  const float* Kb = K + (size_t)b * NKS * DHD;
  const float* Vb = V + (size_t)b * NKS * DHD;

  float* gate_s = (float*)(smem + SM_GATE);
  float* rsbuf  = (float*)(smem + SM_RS);
  float* rsp    = (float*)(smem + SM_RSP);

  // ldmatrix lane addresses (per-warp constant bases) — layouts proven in R8
  const uint32_t aQ0 = sb + SM_Q + (uint32_t)(wm*32 + (m&1)*8 + rr) * QSTR + (m>>1)*16;
  const uint32_t aQ1 = aQ0 + 16 * QSTR;
  const uint32_t bKb = sb + SM_K0 + (uint32_t)(wn*16 + (m>>1)*8 + rr) * KSTR + (m&1)*16;
  const uint32_t aP0 = sb + SM_P + (uint32_t)(wm*32 + (m&1)*8 + rr) * PSTR + (m>>1)*16;
  const uint32_t aP1 = aP0 + 16 * PSTR;
  const uint32_t vBb = sb + SM_V0 + (uint32_t)((m&1)*8 + rr) * VSTR
                       + (uint32_t)(wn*64) + (m>>1)*16;

  // --- gate precompute (includes 1/sqrt(dh)) ---
  for (int k = tid; k < NKS; k += NTHR) {
    float ph = phases[k];
    float pd = fminf(ph, TWO_PI_F - ph);
    gate_s[k] = __expf(-pd * pd * INV2W2_F) * SCALE_F;
  }

  // --- prefetch first K/V tile into registers ---
  const float4* kp4 = (const float4*)Kb;
  const float4* vp4 = (const float4*)Vb;
  float4 pfk[4], pfv[4];
#pragma unroll
  for (int t = 0; t < 4; t++) {
    pfk[t] = kp4[tid + t * NTHR];
    pfv[t] = vp4[tid + t * NTHR];
  }

  // --- Q tile -> SMEM fp16 (128 x 128) ---
  {
    const float4* qp = (const float4*)Qb;
    for (int it = tid; it < 4096; it += NTHR) {
      int row = it >> 5;
      int c4 = (it & 31) << 2;
      *(uint2*)(smem + SM_Q + row * QSTR + c4 * 2) = cvt4h(qp[it]);
    }
  }

  // --- store tile 0 into K/V buffer 0 ---
#pragma unroll
  for (int t = 0; t < 4; t++) {
    int it = tid + t * NTHR;
    int row = it >> 5;
    int c4 = (it & 31) << 2;
    int off = row * KSTR + c4 * 2;
    *(uint2*)(smem + SM_K0 + off) = cvt4h(pfk[t]);
    *(uint2*)(smem + SM_V0 + off) = cvt4h(pfv[t]);
  }
  __syncthreads();

  float o[2][4][4];   // persistent O accumulators: 32 q x 32 dh per warp
#pragma unroll
  for (int i = 0; i < 2; i++)
#pragma unroll
    for (int j = 0; j < 4; j++)
#pragma unroll
      for (int e = 0; e < 4; e++) o[i][j][e] = 0.0f;

  float rs[2][2] = {{0.f,0.f},{0.f,0.f}};

  for (int kt = 0; kt < 32; kt++) {
    const int k0 = kt * 64;
    const uint32_t bufo = (uint32_t)(kt & 1) * KVBUF;

    // --- issue next tile's LDG (hidden behind QK + epilogue + PV) ---
    if (kt < 31) {
      int base = (kt + 1) * 2048;
#pragma unroll
      for (int t = 0; t < 4; t++) {
        pfk[t] = kp4[base + tid + t * NTHR];
        pfv[t] = vp4[base + tid + t * NTHR];
      }
    }

    // --- S = Q K^T  (warp tile 32q x 16k, single-pass fp16) ---
    float s[2][2][4];
#pragma unroll
    for (int i = 0; i < 2; i++)
#pragma unroll
      for (int j = 0; j < 2; j++)
#pragma unroll
        for (int e = 0; e < 4; e++) s[i][j][e] = 0.0f;

#pragma unroll
    for (int kc = 0; kc < 8; kc++) {
      uint32_t a0[4], a1[4], bk[4];
      const uint32_t ko = kc * 32;
      LDSM_X4(a0, aQ0 + ko);
      LDSM_X4(a1, aQ1 + ko);
      LDSM_X4(bk, bKb + bufo + ko);
      MMA16816(s[0][0], a0, bk[0], bk[1]);
      MMA16816(s[1][0], a1, bk[0], bk[1]);
      MMA16816(s[0][1], a0, bk[2], bk[3]);
      MMA16816(s[1][1], a1, bk[2], bk[3]);
    }

    // --- Epilogue: p = exp(s*gate); rowsum; P fp16 -> SMEM; attn STG ---
#pragma unroll
    for (int i = 0; i < 2; i++) {
      const int lr = wm*32 + i*16 + g;
#pragma unroll
      for (int j = 0; j < 2; j++) {
        const int lc = wn*16 + j*8 + 2*c;
        float2 gt = *(const float2*)(smem + SM_GATE + (size_t)(k0 + lc) * 4);
        float p00 = __expf(s[i][j][0] * gt.x);
        float p01 = __expf(s[i][j][1] * gt.y);
        float p10 = __expf(s[i][j][2] * gt.x);
        float p11 = __expf(s[i][j][3] * gt.y);
        rs[i][0] += p00 + p01;
        rs[i][1] += p10 + p11;
        int po = lr * PSTR + lc * 2;
        *(uint32_t*)(smem + SM_P + po)          = pkh2(p00, p01);
        *(uint32_t*)(smem + SM_P + po + 8*PSTR) = pkh2(p10, p11);
        if (write_attn) {
          float* a0 = attn + ((size_t)(b * NQS + q0 + lr)) * NKS + (k0 + lc);
          *(float2*)a0 = make_float2(p00, p01);
          *(float2*)(a0 + (size_t)8 * NKS) = make_float2(p10, p11);
        }
      }
    }
    __syncthreads();   // P visible to all warps

    // --- store next K/V tile into the other buffer (overlaps PV) ---
    if (kt < 31) {
      const uint32_t nb = (uint32_t)((kt + 1) & 1) * KVBUF;
#pragma unroll
      for (int t = 0; t < 4; t++) {
        int it = tid + t * NTHR;
        int row = it >> 5;
        int c4 = (it & 31) << 2;
        int off = row * KSTR + c4 * 2;
        *(uint2*)(smem + SM_K0 + nb + off) = cvt4h(pfk[t]);
        *(uint2*)(smem + SM_V0 + nb + off) = cvt4h(pfv[t]);
      }
    }

    // --- O += P V  (warp tile 32q x 32dh, 64 keys, single-pass fp16) ---
#pragma unroll
    for (int kc = 0; kc < 4; kc++) {
      uint32_t p0[4], p1[4], v0[4], v1[4];
      const uint32_t po = kc * 32;
      const uint32_t vo = bufo + kc * 16 * VSTR;
      LDSM_X4(p0, aP0 + po);
      LDSM_X4(p1, aP1 + po);
      LDSM_X4_T(v0, vBb + vo);
      LDSM_X4_T(v1, vBb + vo + 32);
      MMA16816(o[0][0], p0, v0[0], v0[1]);
      MMA16816(o[1][0], p1, v0[0], v0[1]);
      MMA16816(o[0][1], p0, v0[2], v0[3]);
      MMA16816(o[1][1], p1, v0[2], v0[3]);
      MMA16816(o[0][2], p0, v1[0], v1[1]);
      MMA16816(o[1][2], p1, v1[0], v1[1]);
      MMA16816(o[0][3], p0, v1[2], v1[3]);
      MMA16816(o[1][3], p1, v1[2], v1[3]);
    }
    __syncthreads();   // K/V/P consumed; next iteration may overwrite
  }

  // --- Rowsum: quad shfl -> per-wn partials -> deterministic 4-way combine ---
#pragma unroll
  for (int i = 0; i < 2; i++)
#pragma unroll
    for (int h = 0; h < 2; h++) {
      float v = rs[i][h];
      v += __shfl_xor_sync(0xffffffffu, v, 1);
      v += __shfl_xor_sync(0xffffffffu, v, 2);
      rs[i][h] = v;
    }
  if (c == 0) {
#pragma unroll
    for (int i = 0; i < 2; i++)
#pragma unroll
      for (int h = 0; h < 2; h++)
        rsp[wn * 128 + wm*32 + i*16 + h*8 + g] = rs[i][h];
  }
  __syncthreads();
  if (tid < 128) {
    float rsum = (rsp[tid] + rsp[128 + tid]) + (rsp[256 + tid] + rsp[384 + tid]);
    rsbuf[tid] = 1.0f / rsum;
  }
  __syncthreads();   // rsbuf ready; also orders this CTA's attn STG before reads

  // --- Normalized output store (each warp: 32q x 32dh) ---
#pragma unroll
  for (int i = 0; i < 2; i++) {
    const int lr = wm*32 + i*16 + g;
    const float inv0 = rsbuf[lr];
    const float inv1 = rsbuf[lr + 8];
    float* o0 = out + ((size_t)(b * NQS + q0 + lr)) * DHD + wn*32 + 2*c;
#pragma unroll
    for (int j = 0; j < 4; j++) {
      *(float2*)(o0 + j*8) = make_float2(o[i][j][0] * inv0, o[i][j][1] * inv0);
      *(float2*)(o0 + (size_t)8 * DHD + j*8) =
          make_float2(o[i][j][2] * inv1, o[i][j][3] * inv1);
    }
  }

  // --- Self-normalize this CTA's attention block (fused norm pass) ---
  // Reads values this CTA wrote earlier in this launch (__syncthreads above
  // guarantees visibility); one 2048-f32 row per 512-thread pass => fully
  // coalesced 8KB bursts, broadcast rsbuf[row] read.
  if (write_attn) {
    float4* a4 = (float4*)(attn + ((size_t)(b * NQS + q0)) * NKS);
#pragma unroll 4
    for (int it = tid; it < 65536; it += NTHR) {
      const float inv = rsbuf[it >> 9];   // 512 float4 per row
      float4 v = a4[it];
      v.x *= inv; v.y *= inv; v.z *= inv; v.w *= inv;
      a4[it] = v;
    }
  }
}

// ---------------------------------------------------------------------------
// Launch
// ---------------------------------------------------------------------------
extern "C" void kernel_launch(void* const* d_in, const int* in_sizes, int n_in,
                              void* d_out, int out_size) {
  const float* Q  = (const float*)d_in[0];
  const float* K  = (const float*)d_in[1];
  const float* V  = (const float*)d_in[2];
  const float* ph = (const float*)d_in[3];
  float* out = (float*)d_out;

  const bool write_attn = ((long long)out_size >= (long long)OUT_ELEMS + ATTN_ELEMS);
  float* attn = out + OUT_ELEMS;

  cudaFuncSetAttribute(gpa_main_kernel,
                       cudaFuncAttributeMaxDynamicSharedMemorySize, SMEM_TOTAL);

  dim3 grid(NQS / 128, BB);
  gpa_main_kernel<<<grid, NTHR, SMEM_TOTAL>>>(Q, K, V, ph, out, attn,
                                              write_attn ? 1 : 0);
}